// round 12
// baseline (speedup 1.0000x reference)
#include <cuda_runtime.h>

#define HH 224
#define WW 224
#define STEPS 32
#define NWARP 8
#define RPS 5               // vertex rows per strip: 45 strips * 5 = 225 rows
#define NSTRIPS 45
#define BLOCKS_PER_IMG 45
#define SENT 63             // sentinel bucket (>=32 -> never counted)

// bucket index: smallest k with value <= t_k, t_k = -2 + 4k/31
__device__ __forceinline__ int bucketf(float v) {
    float r = fmaf(v, 7.75f, 15.5f);      // (v + 2) * 31/4
    int k = __float2int_ru(r);            // inf -> INT_MAX (inert, >=32)
    return max(k, 0);
}

// PTX shl.b32 clamps shift >= 32 to produce 0  ->  mbits(x) = all-ones for x >= 32
__device__ __forceinline__ unsigned shl1(int x) {
    unsigned r;
    asm("shl.b32 %0, 1, %1;" : "=r"(r) : "r"(x));
    return r;
}
__device__ __forceinline__ unsigned mbits(int x) { return shl1(x) - 1u; }  // bits [0, min(x,32))

// carry-save add of 1-bit mask m into 3 bitplanes (per-bin counts <= 7)
__device__ __forceinline__ void csa(unsigned& s0, unsigned& s1, unsigned& s2, unsigned m) {
    unsigned c0 = s0 & m; s0 ^= m;
    unsigned c1 = s1 & c0; s1 ^= c0;
    s2 |= c1;
}

// warp-cooperative 32x32 bit-matrix transpose: input bit c of lane r = M[r][c],
// output bit c of lane r = M[c][r]. Recursive block swap, 5 shfl_xor steps.
__device__ __forceinline__ unsigned bit_transpose(unsigned v, int lane) {
    const unsigned full = 0xffffffffu;
    unsigned q;
    q = __shfl_xor_sync(full, v, 16);
    v = (lane & 16) ? ((v & 0xFFFF0000u) | (q >> 16))
                    : ((v & 0x0000FFFFu) | (q << 16));
    q = __shfl_xor_sync(full, v, 8);
    v = (lane & 8)  ? ((v & 0xFF00FF00u) | ((q >> 8) & 0x00FF00FFu))
                    : ((v & 0x00FF00FFu) | ((q << 8) & 0xFF00FF00u));
    q = __shfl_xor_sync(full, v, 4);
    v = (lane & 4)  ? ((v & 0xF0F0F0F0u) | ((q >> 4) & 0x0F0F0F0Fu))
                    : ((v & 0x0F0F0F0Fu) | ((q << 4) & 0xF0F0F0F0u));
    q = __shfl_xor_sync(full, v, 2);
    v = (lane & 2)  ? ((v & 0xCCCCCCCCu) | ((q >> 2) & 0x33333333u))
                    : ((v & 0x33333333u) | ((q << 2) & 0xCCCCCCCCu));
    q = __shfl_xor_sync(full, v, 1);
    v = (lane & 1)  ? ((v & 0xAAAAAAAAu) | ((q >> 1) & 0x55555555u))
                    : ((v & 0x55555555u) | ((q << 1) & 0xAAAAAAAAu));
    return v;
}

__global__ __launch_bounds__(256) void ecc_kernel(const float* __restrict__ x,
                                                  float* __restrict__ out) {
    __shared__ int part[NWARP * 32];
    const int tid = threadIdx.x;
    const int warp = tid >> 5;
    const int lane = tid & 31;

    const int img  = blockIdx.y;
    const float* p = x + (size_t)img * (HH * WW);
    const int cg   = warp;                 // column group == warp id
    const int strip = blockIdx.x;          // 0..44
    const int j    = cg * 32 + lane;       // vertex column
    const int rbase = strip * RPS - 1;

    const bool rc = (strip == 0) | (strip == NSTRIPS - 1);

    // load pixel buckets for columns j and j-1, rows rbase..rbase+RPS (MLP=12)
    int b[RPS + 1], bl[RPS + 1];
    if (!rc && cg >= 1 && cg <= 6) {
        const float* q = p + rbase * WW + j;
#pragma unroll
        for (int r = 0; r <= RPS; r++) {
            b[r]  = bucketf(__ldg(q + r * WW));
            bl[r] = bucketf(__ldg(q + r * WW - 1));
        }
    } else if (!rc) {
        const bool jok  = (unsigned)j < WW;
        const bool jmok = (unsigned)(j - 1) < WW;
        const float* q = p + rbase * WW + j;
#pragma unroll
        for (int r = 0; r <= RPS; r++) {
            b[r]  = jok  ? bucketf(__ldg(q + r * WW))     : SENT;
            bl[r] = jmok ? bucketf(__ldg(q + r * WW - 1)) : SENT;
        }
    } else {
        const bool jok  = (unsigned)j < WW;
        const bool jmok = (unsigned)(j - 1) < WW;
#pragma unroll
        for (int r = 0; r <= RPS; r++) {
            const int rr = rbase + r;
            const bool rok = (unsigned)rr < HH;
            b[r]  = (rok && jok)  ? bucketf(__ldg(p + rr * WW + j))     : SENT;
            bl[r] = (rok && jmok) ? bucketf(__ldg(p + rr * WW + j - 1)) : SENT;
        }
    }

    // per-lane carry-save bitplane accumulators (bit k = bin k), pos/neg separate
    unsigned p0 = 0, p1 = 0, p2 = 0, n0 = 0, n1 = 0, n2 = 0;

#pragma unroll
    for (int r = 1; r <= RPS; r++) {
        const int b_up  = b[r - 1];    // (i-1, j)
        const int b_ul  = bl[r - 1];   // (i-1, j-1)
        const int b_cur = b[r];        // (i,   j)
        const int b_l   = bl[r];       // (i,   j-1)

        const int eh  = min(b_up, b_cur);
        const int ev  = min(b_l,  b_cur);
        const int emn = min(eh, ev);
        const int emx = max(eh, ev);
        const int kv  = min(emn, b_ul);     // kv <= emn <= emx <= kf
        const int kf  = b_cur;

        // cumulative-ECC contribution at bin k: +[kv<=k<emn] - [emx<=k<kf]
        const unsigned mp = mbits(emn) ^ mbits(kv);
        const unsigned mn = mbits(kf)  ^ mbits(emx);
        csa(p0, p1, p2, mp);
        csa(n0, n1, n2, mn);
    }

    // warp epilogue: transpose each bitplane so lane k holds bin-k bits across lanes
    {
        int cnt =     __popc(bit_transpose(p0, lane))
                + 2 * __popc(bit_transpose(p1, lane))
                + 4 * __popc(bit_transpose(p2, lane))
                -     __popc(bit_transpose(n0, lane))
                - 2 * __popc(bit_transpose(n1, lane))
                - 4 * __popc(bit_transpose(n2, lane));
        part[warp * 32 + lane] = cnt;
    }
    __syncthreads();

    // block reduce (masks already encode cumulative semantics -> no scan)
    if (tid < 32) {
        int v = 0;
#pragma unroll
        for (int w = 0; w < NWARP; w++) v += part[w * 32 + tid];
        atomicAdd(out + img * 32 + tid, (float)v);
    }
}

extern "C" void kernel_launch(void* const* d_in, const int* in_sizes, int n_in,
                              void* d_out, int out_size) {
    const float* x = (const float*)d_in[0];
    float* out = (float*)d_out;
    const int imgs = in_sizes[0] / (HH * WW);   // 8*3 = 24

    cudaMemsetAsync(out, 0, (size_t)out_size * sizeof(float), 0);
    dim3 grid(BLOCKS_PER_IMG, imgs);
    ecc_kernel<<<grid, 256>>>(x, out);
}

// round 13
// speedup vs baseline: 1.2237x; 1.2237x over previous
#include <cuda_runtime.h>

#define HH 224
#define WW 224
#define STEPS 32
#define NWARP 8
#define RPS 7               // rows per strip (CSA capacity limit: counts <= 7)
#define NSTRIPS 33          // 33 * 7 = 231 >= 225 vertex rows
#define SENTG 0u            // sentinel ge-mask: counts at no threshold

// PTX shl.b32 clamps shift >= 32 -> result 0
__device__ __forceinline__ unsigned shl1(int x) {
    unsigned r;
    asm("shl.b32 %0, 1, %1;" : "=r"(r) : "r"(x));
    return r;
}

// ge-mask of a pixel: bit t set iff bucket(v) <= t  (i.e. cell counted at threshold t)
// bucket k = max(0, ceil((v+2)*31/4)); ge(k) = ~((1<<k)-1) = -(1<<k); k>=32 -> 0
__device__ __forceinline__ unsigned gmask(float v) {
    float r = fmaf(v, 7.75f, 15.5f);
    int k = max(__float2int_ru(r), 0);
    return 0u - shl1(k);
}

// carry-save add of 1-bit mask m into 3 bitplanes (per-bin counts <= 7)
__device__ __forceinline__ void csa(unsigned& s0, unsigned& s1, unsigned& s2, unsigned m) {
    unsigned c0 = s0 & m; s0 ^= m;
    unsigned c1 = s1 & c0; s1 ^= c0;
    s2 |= c1;
}

// warp-cooperative 32x32 bit-matrix transpose (5 shfl_xor block-swap steps)
__device__ __forceinline__ unsigned bit_transpose(unsigned v, int lane) {
    const unsigned full = 0xffffffffu;
    unsigned q;
    q = __shfl_xor_sync(full, v, 16);
    v = (lane & 16) ? ((v & 0xFFFF0000u) | (q >> 16))
                    : ((v & 0x0000FFFFu) | (q << 16));
    q = __shfl_xor_sync(full, v, 8);
    v = (lane & 8)  ? ((v & 0xFF00FF00u) | ((q >> 8) & 0x00FF00FFu))
                    : ((v & 0x00FF00FFu) | ((q << 8) & 0xFF00FF00u));
    q = __shfl_xor_sync(full, v, 4);
    v = (lane & 4)  ? ((v & 0xF0F0F0F0u) | ((q >> 4) & 0x0F0F0F0Fu))
                    : ((v & 0x0F0F0F0Fu) | ((q << 4) & 0xF0F0F0F0u));
    q = __shfl_xor_sync(full, v, 2);
    v = (lane & 2)  ? ((v & 0xCCCCCCCCu) | ((q >> 2) & 0x33333333u))
                    : ((v & 0x33333333u) | ((q << 2) & 0xCCCCCCCCu));
    q = __shfl_xor_sync(full, v, 1);
    v = (lane & 1)  ? ((v & 0xAAAAAAAAu) | ((q >> 1) & 0x55555555u))
                    : ((v & 0x55555555u) | ((q << 1) & 0xAAAAAAAAu));
    return v;
}

__global__ __launch_bounds__(256) void ecc_kernel(const float* __restrict__ x,
                                                  float* __restrict__ out) {
    __shared__ int part[NWARP * 32];
    const int tid = threadIdx.x;
    const int warp = tid >> 5;
    const int lane = tid & 31;

    const int img  = blockIdx.y;
    const float* p = x + (size_t)img * (HH * WW);
    const int cg   = warp;                 // column group == warp id
    const int strip = blockIdx.x;          // 0..32
    const int j    = cg * 32 + lane;       // vertex column (>=225 inert via guards)
    const int rbase = strip * RPS - 1;

    const bool rc = (strip == 0) | (strip == NSTRIPS - 1);

    // ge-masks for pixels at columns j and j-1, rows rbase..rbase+RPS (MLP=16)
    unsigned g[RPS + 1], gl[RPS + 1];
    if (!rc && cg >= 1 && cg <= 6) {
        const float* q = p + rbase * WW + j;
#pragma unroll
        for (int r = 0; r <= RPS; r++) {
            g[r]  = gmask(__ldg(q + r * WW));
            gl[r] = gmask(__ldg(q + r * WW - 1));
        }
    } else if (!rc) {
        const bool jok  = (unsigned)j < WW;
        const bool jmok = (unsigned)(j - 1) < WW;
        const float* q = p + rbase * WW + j;
#pragma unroll
        for (int r = 0; r <= RPS; r++) {
            g[r]  = jok  ? gmask(__ldg(q + r * WW))     : SENTG;
            gl[r] = jmok ? gmask(__ldg(q + r * WW - 1)) : SENTG;
        }
    } else {
        const bool jok  = (unsigned)j < WW;
        const bool jmok = (unsigned)(j - 1) < WW;
#pragma unroll
        for (int r = 0; r <= RPS; r++) {
            const int rr = rbase + r;
            const bool rok = (unsigned)rr < HH;
            g[r]  = (rok && jok)  ? gmask(__ldg(p + rr * WW + j))     : SENTG;
            gl[r] = (rok && jmok) ? gmask(__ldg(p + rr * WW + j - 1)) : SENTG;
        }
    }

    // per-lane carry-save bitplanes (bit t = threshold t), pos/neg separate
    unsigned p0 = 0, p1 = 0, p2 = 0, n0 = 0, n1 = 0, n2 = 0;

#pragma unroll
    for (int r = 1; r <= RPS; r++) {
        const unsigned G_up  = g[r - 1];   // (i-1, j)
        const unsigned G_ul  = gl[r - 1];  // (i-1, j-1)
        const unsigned G_cur = g[r];       // (i,   j)
        const unsigned G_l   = gl[r];      // (i,   j-1)

        // contribution at threshold t: ge(kv) - ge(eh) - ge(ev) + ge(kf)
        //   = +1 on  G_ul & ~(G_up|G_l|G_cur)
        //   = -1 on  (G_up & G_l) & ~G_cur
        const unsigned mp = G_ul & ~(G_up | G_l | G_cur);
        const unsigned mn = (G_up & G_l) & ~G_cur;
        csa(p0, p1, p2, mp);
        csa(n0, n1, n2, mn);
    }

    // warp epilogue: transpose bitplanes so lane t holds threshold-t bits
    {
        int cnt =     __popc(bit_transpose(p0, lane))
                + 2 * __popc(bit_transpose(p1, lane))
                + 4 * __popc(bit_transpose(p2, lane))
                -     __popc(bit_transpose(n0, lane))
                - 2 * __popc(bit_transpose(n1, lane))
                - 4 * __popc(bit_transpose(n2, lane));
        part[warp * 32 + lane] = cnt;
    }
    __syncthreads();

    // block reduce (ge-masks already cumulative -> no scan)
    if (tid < 32) {
        int v = 0;
#pragma unroll
        for (int w = 0; w < NWARP; w++) v += part[w * 32 + tid];
        atomicAdd(out + img * 32 + tid, (float)v);
    }
}

extern "C" void kernel_launch(void* const* d_in, const int* in_sizes, int n_in,
                              void* d_out, int out_size) {
    const float* x = (const float*)d_in[0];
    float* out = (float*)d_out;
    const int imgs = in_sizes[0] / (HH * WW);   // 8*3 = 24

    cudaMemsetAsync(out, 0, (size_t)out_size * sizeof(float), 0);
    dim3 grid(NSTRIPS, imgs);
    ecc_kernel<<<grid, 256>>>(x, out);
}